// round 5
// baseline (speedup 1.0000x reference)
#include <cuda_runtime.h>

// HyperMLP 128->512->512->512->128 per-sample weights streamed from z.
// Split into 4 layer kernels for fine-grained load balance; activations
// ping-pong through __device__ scratch.

#define NBATCH 512
#define TOTAL_PARAMS 657024

#define W1_OFF 0          // 128*512
#define B1_OFF 65536      // 512
#define W2_OFF 66048      // 512*512
#define B2_OFF 328192     // 512
#define W3_OFF 328704     // 512*512
#define B3_OFF 590848     // 512
#define W4_OFF 591360     // 512*128
#define B4_OFF 656896     // 128

__device__ float g_act1[NBATCH * 512];
__device__ float g_act2[NBATCH * 512];

// ---------------- Layer 1: din=128, dout=512, relu ----------------
// grid = NBATCH*4, block = 256. CTA = (sample, 128-output slice).
__global__ __launch_bounds__(256, 8)
void l1_kernel(const float* __restrict__ z, const float* __restrict__ xq)
{
    const int b = blockIdx.x >> 2;
    const int s = blockIdx.x & 3;                 // output slice (128 outs)
    const float* __restrict__ zb = z + (size_t)b * TOTAL_PARAMS;
    const int t = threadIdx.x;

    __shared__ float xs[128];
    __shared__ float red[8 * 128];

    if (t < 128) xs[t] = xq[b * 128 + t];
    __syncthreads();

    const float4* __restrict__ wv = (const float4*)(zb + W1_OFF); // row = 128 float4
    const int lane = t & 31;                      // 32 float4 = 128 outputs
    const int g    = t >> 5;                      // 8 groups x 16 i
    float4 acc = make_float4(0.f, 0.f, 0.f, 0.f);
    #pragma unroll 8
    for (int i = g * 16; i < g * 16 + 16; ++i) {
        const float xi = xs[i];
        const float4 wq = __ldcs(&wv[i * 128 + s * 32 + lane]);
        acc.x = fmaf(xi, wq.x, acc.x);
        acc.y = fmaf(xi, wq.y, acc.y);
        acc.z = fmaf(xi, wq.z, acc.z);
        acc.w = fmaf(xi, wq.w, acc.w);
    }
    ((float4*)(red + g * 128))[lane] = acc;
    __syncthreads();
    if (t < 128) {
        float v = zb[B1_OFF + s * 128 + t];
        #pragma unroll
        for (int g2 = 0; g2 < 8; ++g2) v += red[g2 * 128 + t];
        g_act1[b * 512 + s * 128 + t] = fmaxf(v, 0.f);
    }
}

// ---------------- Layers 2/3: din=512, dout=512, relu ----------------
// grid = NBATCH*4, block = 256. CTA = (sample, 128-output slice).
__global__ __launch_bounds__(256, 8)
void lmid_kernel(const float* __restrict__ z,
                 const float* __restrict__ act_in,
                 float* __restrict__ act_out,
                 int w_off, int b_off)
{
    const int b = blockIdx.x >> 2;
    const int s = blockIdx.x & 3;
    const float* __restrict__ zb = z + (size_t)b * TOTAL_PARAMS;
    const int t = threadIdx.x;

    __shared__ float xs[512];
    __shared__ float red[8 * 128];

    xs[t]       = act_in[b * 512 + t];
    xs[t + 256] = act_in[b * 512 + t + 256];
    __syncthreads();

    const float4* __restrict__ wv = (const float4*)(zb + w_off);
    const int lane = t & 31;
    const int g    = t >> 5;                      // 8 groups x 64 i
    float4 acc = make_float4(0.f, 0.f, 0.f, 0.f);
    #pragma unroll 8
    for (int i = g * 64; i < g * 64 + 64; ++i) {
        const float xi = xs[i];
        const float4 wq = __ldcs(&wv[i * 128 + s * 32 + lane]);
        acc.x = fmaf(xi, wq.x, acc.x);
        acc.y = fmaf(xi, wq.y, acc.y);
        acc.z = fmaf(xi, wq.z, acc.z);
        acc.w = fmaf(xi, wq.w, acc.w);
    }
    ((float4*)(red + g * 128))[lane] = acc;
    __syncthreads();
    if (t < 128) {
        float v = zb[b_off + s * 128 + t];
        #pragma unroll
        for (int g2 = 0; g2 < 8; ++g2) v += red[g2 * 128 + t];
        act_out[b * 512 + s * 128 + t] = fmaxf(v, 0.f);
    }
}

// ---------------- Layer 4: din=512, dout=128, no relu ----------------
// grid = NBATCH*2, block = 256. CTA = (sample, 64-output slice).
__global__ __launch_bounds__(256, 8)
void l4_kernel(const float* __restrict__ z,
               const float* __restrict__ act_in,
               float* __restrict__ out)
{
    const int b = blockIdx.x >> 1;
    const int s = blockIdx.x & 1;                 // 64-output slice
    const float* __restrict__ zb = z + (size_t)b * TOTAL_PARAMS;
    const int t = threadIdx.x;

    __shared__ float xs[512];
    __shared__ float red[16 * 64];

    xs[t]       = act_in[b * 512 + t];
    xs[t + 256] = act_in[b * 512 + t + 256];
    __syncthreads();

    const float4* __restrict__ wv = (const float4*)(zb + W4_OFF); // row = 32 float4
    const int lane = t & 15;                      // 16 float4 = 64 outputs
    const int g    = t >> 4;                      // 16 groups x 32 i
    float4 acc = make_float4(0.f, 0.f, 0.f, 0.f);
    #pragma unroll 8
    for (int i = g * 32; i < g * 32 + 32; ++i) {
        const float xi = xs[i];
        const float4 wq = __ldcs(&wv[i * 32 + s * 16 + lane]);
        acc.x = fmaf(xi, wq.x, acc.x);
        acc.y = fmaf(xi, wq.y, acc.y);
        acc.z = fmaf(xi, wq.z, acc.z);
        acc.w = fmaf(xi, wq.w, acc.w);
    }
    ((float4*)(red + g * 64))[lane] = acc;
    __syncthreads();
    if (t < 64) {
        float v = zb[B4_OFF + s * 64 + t];
        #pragma unroll
        for (int g2 = 0; g2 < 16; ++g2) v += red[g2 * 64 + t];
        out[b * 128 + s * 64 + t] = v;
    }
}

extern "C" void kernel_launch(void* const* d_in, const int* in_sizes, int n_in,
                              void* d_out, int out_size)
{
    const float* z  = (const float*)d_in[0];
    const float* xq = (const float*)d_in[1];
    if (n_in >= 2 && in_sizes[0] == NBATCH * 128) {
        z  = (const float*)d_in[1];
        xq = (const float*)d_in[0];
    }
    float* out = (float*)d_out;

    float* a1; cudaGetSymbolAddress((void**)&a1, g_act1);
    float* a2; cudaGetSymbolAddress((void**)&a2, g_act2);

    l1_kernel<<<NBATCH * 4, 256>>>(z, xq);
    lmid_kernel<<<NBATCH * 4, 256>>>(z, a1, a2, W2_OFF, B2_OFF);
    lmid_kernel<<<NBATCH * 4, 256>>>(z, a2, a1, W3_OFF, B3_OFF);
    l4_kernel<<<NBATCH * 2, 256>>>(z, a1, out);
}

// round 7
// speedup vs baseline: 1.1499x; 1.1499x over previous
#include <cuda_runtime.h>
#include <cooperative_groups.h>

namespace cg = cooperative_groups;

// HyperMLP 128->512->512->512->128, per-sample weights streamed from z.
// Monolithic kernel, 2-CTA cluster per sample: each 256-thread CTA computes
// half of each layer's outputs; activation halves exchanged via DSMEM.

#define NBATCH 512
#define TOTAL_PARAMS 657024

#define W1_OFF 0          // 128*512
#define B1_OFF 65536      // 512
#define W2_OFF 66048      // 512*512
#define B2_OFF 328192     // 512
#define W3_OFF 328704     // 512*512
#define B3_OFF 590848     // 512
#define W4_OFF 591360     // 512*128
#define B4_OFF 656896     // 128

__global__ __launch_bounds__(256, 8) __cluster_dims__(2, 1, 1)
void hypermlp_kernel(const float* __restrict__ z,
                     const float* __restrict__ xq,
                     float* __restrict__ out)
{
    cg::cluster_group cluster = cg::this_cluster();
    const int r    = (int)cluster.block_rank();   // 0 or 1
    const int peer = r ^ 1;
    const int b    = blockIdx.x >> 1;             // sample
    const float* __restrict__ zb = z + (size_t)b * TOTAL_PARAMS;
    const int t = threadIdx.x;                    // 0..255

    __shared__ float xs[512];                     // full activation vector
    __shared__ float red[1024];                   // 4KB partial-sum buffer

    // Load input x_q[b, 0:128]
    if (t < 128) xs[t] = xq[b * 128 + t];
    __syncthreads();

    // ---------------- Layer 1: din=128, dout=512 (CTA: 256 outs) ----------------
    {
        const float4* __restrict__ wv = (const float4*)(zb + W1_OFF); // row = 128 f4
        const int lane = t & 63;                  // 64 float4 = 256 outputs
        const int g    = t >> 6;                  // 4 groups x 32 i
        float4 acc = make_float4(0.f, 0.f, 0.f, 0.f);
        #pragma unroll 8
        for (int i = g * 32; i < g * 32 + 32; ++i) {
            const float xi = xs[i];
            const float4 wq = __ldcs(&wv[i * 128 + r * 64 + lane]);
            acc.x = fmaf(xi, wq.x, acc.x);
            acc.y = fmaf(xi, wq.y, acc.y);
            acc.z = fmaf(xi, wq.z, acc.z);
            acc.w = fmaf(xi, wq.w, acc.w);
        }
        ((float4*)(red + g * 256))[lane] = acc;
        __syncthreads();
        float v = zb[B1_OFF + r * 256 + t];
        #pragma unroll
        for (int g2 = 0; g2 < 4; ++g2) v += red[g2 * 256 + t];
        xs[r * 256 + t] = fmaxf(v, 0.f);
        // exchange halves
        cluster.sync();
        const float* pxs = (const float*)cluster.map_shared_rank(xs, peer);
        xs[peer * 256 + t] = pxs[peer * 256 + t];
        __syncthreads();
    }

    // ---------------- Layers 2 & 3: din=512, dout=512 ----------------
    {
        const float* p = zb + W2_OFF;
        #pragma unroll 1
        for (int L = 0; L < 2; ++L) {
            const float4* __restrict__ wv = (const float4*)p;
            const float* __restrict__ bias = p + 512 * 512;
            const int lane = t & 63;
            const int g    = t >> 6;              // 4 groups x 128 i
            float4 acc = make_float4(0.f, 0.f, 0.f, 0.f);
            #pragma unroll 8
            for (int i = g * 128; i < g * 128 + 128; ++i) {
                const float xi = xs[i];
                const float4 wq = __ldcs(&wv[i * 128 + r * 64 + lane]);
                acc.x = fmaf(xi, wq.x, acc.x);
                acc.y = fmaf(xi, wq.y, acc.y);
                acc.z = fmaf(xi, wq.z, acc.z);
                acc.w = fmaf(xi, wq.w, acc.w);
            }
            ((float4*)(red + g * 256))[lane] = acc;
            __syncthreads();
            float v = bias[r * 256 + t];
            #pragma unroll
            for (int g2 = 0; g2 < 4; ++g2) v += red[g2 * 256 + t];
            xs[r * 256 + t] = fmaxf(v, 0.f);
            cluster.sync();
            const float* pxs = (const float*)cluster.map_shared_rank(xs, peer);
            xs[peer * 256 + t] = pxs[peer * 256 + t];
            __syncthreads();
            p += 512 * 512 + 512;
        }
    }

    // ---------------- Layer 4: din=512, dout=128 (CTA: 64 outs, no relu) -------
    {
        const float4* __restrict__ wv = (const float4*)(zb + W4_OFF); // row = 32 f4
        const int lane = t & 15;                  // 16 float4 = 64 outputs
        const int g    = t >> 4;                  // 16 groups x 32 i
        float4 acc = make_float4(0.f, 0.f, 0.f, 0.f);
        #pragma unroll 8
        for (int i = g * 32; i < g * 32 + 32; ++i) {
            const float xi = xs[i];
            const float4 wq = __ldcs(&wv[i * 32 + r * 16 + lane]);
            acc.x = fmaf(xi, wq.x, acc.x);
            acc.y = fmaf(xi, wq.y, acc.y);
            acc.z = fmaf(xi, wq.z, acc.z);
            acc.w = fmaf(xi, wq.w, acc.w);
        }
        ((float4*)(red + g * 64))[lane] = acc;    // red as [16][64]
        __syncthreads();
        if (t < 64) {
            float v = zb[B4_OFF + r * 64 + t];
            #pragma unroll
            for (int g2 = 0; g2 < 16; ++g2) v += red[g2 * 64 + t];
            out[b * 128 + r * 64 + t] = v;
        }
    }

    // DSMEM safety: no CTA exits while its peer might still read its xs.
    cluster.sync();
}

extern "C" void kernel_launch(void* const* d_in, const int* in_sizes, int n_in,
                              void* d_out, int out_size)
{
    const float* z  = (const float*)d_in[0];
    const float* xq = (const float*)d_in[1];
    if (n_in >= 2 && in_sizes[0] == NBATCH * 128) {
        z  = (const float*)d_in[1];
        xq = (const float*)d_in[0];
    }
    float* out = (float*)d_out;
    hypermlp_kernel<<<NBATCH * 2, 256>>>(z, xq, out);
}

// round 8
// speedup vs baseline: 1.1668x; 1.0147x over previous
#include <cuda_runtime.h>
#include <cooperative_groups.h>

namespace cg = cooperative_groups;

// HyperMLP 128->512->512->512->128, per-sample weights streamed from z.
// Monolithic kernel, 2-CTA cluster per sample. Each 256-thread CTA computes
// half of each layer's outputs and PUSHES its half into the peer's
// double-buffered activation array via DSMEM (one cluster.sync per layer).
// Chip is at the LTS throughput ceiling (~6.9 TB/s); this round shaves
// barrier/tail overhead only.

#define NBATCH 512
#define TOTAL_PARAMS 657024

#define W1_OFF 0          // 128*512
#define B1_OFF 65536      // 512
#define W2_OFF 66048      // 512*512
#define B2_OFF 328192     // 512
#define W3_OFF 328704     // 512*512
#define B3_OFF 590848     // 512
#define W4_OFF 591360     // 512*128
#define B4_OFF 656896     // 128

__global__ __launch_bounds__(256, 8) __cluster_dims__(2, 1, 1)
void hypermlp_kernel(const float* __restrict__ z,
                     const float* __restrict__ xq,
                     float* __restrict__ out)
{
    cg::cluster_group cluster = cg::this_cluster();
    const int r    = (int)cluster.block_rank();   // 0 or 1
    const int peer = r ^ 1;
    const int b    = blockIdx.x >> 1;             // sample
    const float* __restrict__ zb = z + (size_t)b * TOTAL_PARAMS;
    const int t = threadIdx.x;                    // 0..255

    __shared__ float xs[2][512];                  // double-buffered activations
    __shared__ float red[1024];                   // 4KB partial-sum buffer

    // Peer's xs base (for push exchange)
    float (*pxs)[512] = (float (*)[512])cluster.map_shared_rank(xs, peer);

    // Load input x_q[b, 0:128] into buffer 0
    if (t < 128) xs[0][t] = xq[b * 128 + t];
    __syncthreads();

    const int o = r * 256 + t;                    // this thread's output index

    // ---------------- Layer 1: din=128, dout=512 (CTA: 256 outs) ----------------
    {
        const float4* __restrict__ wv = (const float4*)(zb + W1_OFF); // row = 128 f4
        const int lane = t & 63;                  // 64 float4 = 256 outputs
        const int g    = t >> 6;                  // 4 groups x 32 i
        float4 acc = make_float4(0.f, 0.f, 0.f, 0.f);
        #pragma unroll 8
        for (int i = g * 32; i < g * 32 + 32; ++i) {
            const float xi = xs[0][i];
            const float4 wq = __ldcs(&wv[i * 128 + r * 64 + lane]);
            acc.x = fmaf(xi, wq.x, acc.x);
            acc.y = fmaf(xi, wq.y, acc.y);
            acc.z = fmaf(xi, wq.z, acc.z);
            acc.w = fmaf(xi, wq.w, acc.w);
        }
        ((float4*)(red + g * 256))[lane] = acc;
        __syncthreads();
        float v = zb[B1_OFF + o];
        #pragma unroll
        for (int g2 = 0; g2 < 4; ++g2) v += red[g2 * 256 + t];
        v = fmaxf(v, 0.f);
        xs[1][o]  = v;                            // local half into buffer 1
        pxs[1][o] = v;                            // push same half into peer's buffer 1
        cluster.sync();                           // pushes visible + red reuse safe
    }

    // ---------------- Layers 2 & 3: din=512, dout=512 ----------------
    {
        const float* p = zb + W2_OFF;
        #pragma unroll 1
        for (int L = 0; L < 2; ++L) {
            const int cur = 1 - L;                // L2 reads buf1, L3 reads buf0
            const int nxt = L;                    // L2 writes buf0, L3 writes buf1
            const float4* __restrict__ wv = (const float4*)p;
            const float* __restrict__ bias = p + 512 * 512;
            const int lane = t & 63;
            const int g    = t >> 6;              // 4 groups x 128 i
            float4 acc = make_float4(0.f, 0.f, 0.f, 0.f);
            #pragma unroll 8
            for (int i = g * 128; i < g * 128 + 128; ++i) {
                const float xi = xs[cur][i];
                const float4 wq = __ldcs(&wv[i * 128 + r * 64 + lane]);
                acc.x = fmaf(xi, wq.x, acc.x);
                acc.y = fmaf(xi, wq.y, acc.y);
                acc.z = fmaf(xi, wq.z, acc.z);
                acc.w = fmaf(xi, wq.w, acc.w);
            }
            ((float4*)(red + g * 256))[lane] = acc;
            __syncthreads();
            float v = bias[o];
            #pragma unroll
            for (int g2 = 0; g2 < 4; ++g2) v += red[g2 * 256 + t];
            v = fmaxf(v, 0.f);
            xs[nxt][o]  = v;
            pxs[nxt][o] = v;
            cluster.sync();
            p += 512 * 512 + 512;
        }
    }

    // ---------------- Layer 4: din=512, dout=128 (CTA: 64 outs, no relu) -------
    // Reads xs[1]; no DSMEM traffic after the last cluster.sync, so no trailing
    // cluster barrier is needed.
    {
        const float4* __restrict__ wv = (const float4*)(zb + W4_OFF); // row = 32 f4
        const int lane = t & 15;                  // 16 float4 = 64 outputs
        const int g    = t >> 4;                  // 16 groups x 32 i
        float4 acc = make_float4(0.f, 0.f, 0.f, 0.f);
        #pragma unroll 8
        for (int i = g * 32; i < g * 32 + 32; ++i) {
            const float xi = xs[1][i];
            const float4 wq = __ldcs(&wv[i * 32 + r * 16 + lane]);
            acc.x = fmaf(xi, wq.x, acc.x);
            acc.y = fmaf(xi, wq.y, acc.y);
            acc.z = fmaf(xi, wq.z, acc.z);
            acc.w = fmaf(xi, wq.w, acc.w);
        }
        ((float4*)(red + g * 64))[lane] = acc;    // red as [16][64]
        __syncthreads();
        if (t < 64) {
            float v = zb[B4_OFF + r * 64 + t];
            #pragma unroll
            for (int g2 = 0; g2 < 16; ++g2) v += red[g2 * 64 + t];
            out[b * 128 + r * 64 + t] = v;
        }
    }
}

extern "C" void kernel_launch(void* const* d_in, const int* in_sizes, int n_in,
                              void* d_out, int out_size)
{
    const float* z  = (const float*)d_in[0];
    const float* xq = (const float*)d_in[1];
    if (n_in >= 2 && in_sizes[0] == NBATCH * 128) {
        z  = (const float*)d_in[1];
        xq = (const float*)d_in[0];
    }
    float* out = (float*)d_out;
    hypermlp_kernel<<<NBATCH * 2, 256>>>(z, xq, out);
}

// round 10
// speedup vs baseline: 1.7886x; 1.5329x over previous
#include <cuda_runtime.h>
#include <cooperative_groups.h>

namespace cg = cooperative_groups;

// HyperMLP 128->512->512->512->128, per-sample weights streamed from z.
// 2-CTA cluster per sample, half the outputs per CTA, DSMEM push exchange
// (structure identical to the passing R8 kernel). ONE change vs R8:
// ReLU sparsity — ~50% of activations are exactly 0, and the branch
// `if (xi != 0)` (warp-uniform: xi is broadcast from shared) skips the
// weight-row load entirely, halving DRAM traffic for layers 2-4.

#define NBATCH 512
#define TOTAL_PARAMS 657024

#define W1_OFF 0          // 128*512
#define B1_OFF 65536      // 512
#define W2_OFF 66048      // 512*512
#define B2_OFF 328192     // 512
#define W3_OFF 328704     // 512*512
#define B3_OFF 590848     // 512
#define W4_OFF 591360     // 512*128
#define B4_OFF 656896     // 128

__global__ __launch_bounds__(256, 8) __cluster_dims__(2, 1, 1)
void hypermlp_kernel(const float* __restrict__ z,
                     const float* __restrict__ xq,
                     float* __restrict__ out)
{
    cg::cluster_group cluster = cg::this_cluster();
    const int r    = (int)cluster.block_rank();   // 0 or 1
    const int peer = r ^ 1;
    const int b    = blockIdx.x >> 1;             // sample
    const float* __restrict__ zb = z + (size_t)b * TOTAL_PARAMS;
    const int t = threadIdx.x;                    // 0..255

    __shared__ float xs[2][512];                  // double-buffered activations
    __shared__ float red[1024];                   // 4KB partial-sum buffer

    float (*pxs)[512] = (float (*)[512])cluster.map_shared_rank(xs, peer);

    if (t < 128) xs[0][t] = xq[b * 128 + t];
    __syncthreads();

    const int o = r * 256 + t;                    // this thread's output index

    // ---------------- Layer 1: din=128 (dense input), dout=512 ----------------
    {
        const float4* __restrict__ wv = (const float4*)(zb + W1_OFF); // row=128 f4
        const int lane = t & 63;                  // 64 float4 = 256 outputs
        const int g    = t >> 6;                  // 4 groups x 32 i
        float4 acc = make_float4(0.f, 0.f, 0.f, 0.f);
        #pragma unroll 8
        for (int i = g * 32; i < g * 32 + 32; ++i) {
            const float xi = xs[0][i];
            const float4 wq = __ldcs(&wv[i * 128 + r * 64 + lane]);
            acc.x = fmaf(xi, wq.x, acc.x);
            acc.y = fmaf(xi, wq.y, acc.y);
            acc.z = fmaf(xi, wq.z, acc.z);
            acc.w = fmaf(xi, wq.w, acc.w);
        }
        ((float4*)(red + g * 256))[lane] = acc;
        __syncthreads();
        float v = zb[B1_OFF + o];
        #pragma unroll
        for (int g2 = 0; g2 < 4; ++g2) v += red[g2 * 256 + t];
        v = fmaxf(v, 0.f);
        xs[1][o]  = v;
        pxs[1][o] = v;
        cluster.sync();
    }

    // ---------------- Layers 2 & 3: din=512 (relu-sparse), dout=512 -----------
    {
        const float* p = zb + W2_OFF;
        #pragma unroll 1
        for (int L = 0; L < 2; ++L) {
            const int cur = 1 - L;                // L2 reads buf1, L3 reads buf0
            const int nxt = L;
            const float4* __restrict__ wv = (const float4*)p;
            const float* __restrict__ bias = p + 512 * 512;
            const int lane = t & 63;
            const int g    = t >> 6;              // 4 groups x 128 i
            float4 acc = make_float4(0.f, 0.f, 0.f, 0.f);
            #pragma unroll 4
            for (int i = g * 128; i < g * 128 + 128; ++i) {
                const float xi = xs[cur][i];      // uniform across group
                if (xi != 0.f) {                  // warp-uniform: skip zero rows
                    const float4 wq = __ldcs(&wv[i * 128 + r * 64 + lane]);
                    acc.x = fmaf(xi, wq.x, acc.x);
                    acc.y = fmaf(xi, wq.y, acc.y);
                    acc.z = fmaf(xi, wq.z, acc.z);
                    acc.w = fmaf(xi, wq.w, acc.w);
                }
            }
            ((float4*)(red + g * 256))[lane] = acc;
            __syncthreads();
            float v = bias[o];
            #pragma unroll
            for (int g2 = 0; g2 < 4; ++g2) v += red[g2 * 256 + t];
            v = fmaxf(v, 0.f);
            xs[nxt][o]  = v;
            pxs[nxt][o] = v;
            cluster.sync();
            p += 512 * 512 + 512;
        }
    }

    // ---------------- Layer 4: din=512 (relu-sparse), dout=128, no relu -------
    {
        const float4* __restrict__ wv = (const float4*)(zb + W4_OFF); // row=32 f4
        const int lane = t & 15;                  // 16 float4 = 64 outputs
        const int g    = t >> 4;                  // 16 groups x 32 i
        float4 acc = make_float4(0.f, 0.f, 0.f, 0.f);
        #pragma unroll 4
        for (int i = g * 32; i < g * 32 + 32; ++i) {
            const float xi = xs[1][i];
            if (xi != 0.f) {
                const float4 wq = __ldcs(&wv[i * 32 + r * 16 + lane]);
                acc.x = fmaf(xi, wq.x, acc.x);
                acc.y = fmaf(xi, wq.y, acc.y);
                acc.z = fmaf(xi, wq.z, acc.z);
                acc.w = fmaf(xi, wq.w, acc.w);
            }
        }
        ((float4*)(red + g * 64))[lane] = acc;    // red as [16][64]
        __syncthreads();
        if (t < 64) {
            float v = zb[B4_OFF + r * 64 + t];
            #pragma unroll
            for (int g2 = 0; g2 < 16; ++g2) v += red[g2 * 64 + t];
            out[b * 128 + r * 64 + t] = v;
        }
    }
}

extern "C" void kernel_launch(void* const* d_in, const int* in_sizes, int n_in,
                              void* d_out, int out_size)
{
    const float* z  = (const float*)d_in[0];
    const float* xq = (const float*)d_in[1];
    if (n_in >= 2 && in_sizes[0] == NBATCH * 128) {
        z  = (const float*)d_in[1];
        xq = (const float*)d_in[0];
    }
    float* out = (float*)d_out;
    hypermlp_kernel<<<NBATCH * 2, 256>>>(z, xq, out);
}

// round 11
// speedup vs baseline: 1.8732x; 1.0473x over previous
#include <cuda_runtime.h>
#include <cooperative_groups.h>

namespace cg = cooperative_groups;

// HyperMLP 128->512->512->512->128, per-sample weights streamed from z.
// 2-CTA cluster per sample, DSMEM push exchange (R8 structure).
// ReLU sparsity: ~50% of activations are exactly 0 -> skip those weight rows.
// R11: zero-skip via PREDICATED ld.global.cs (inline PTX), not a branch, so
// unrolled loads stay front-batched (high MLP) while skipped rows still
// issue no memory transaction.

#define NBATCH 512
#define TOTAL_PARAMS 657024

#define W1_OFF 0          // 128*512
#define B1_OFF 65536      // 512
#define W2_OFF 66048      // 512*512
#define B2_OFF 328192     // 512
#define W3_OFF 328704     // 512*512
#define B3_OFF 590848     // 512
#define W4_OFF 591360     // 512*128
#define B4_OFF 656896     // 128

// Predicated streaming float4 load: returns w (= *p) if x != 0, else 0s.
// No branch: @p ld.global.cs.v4 — issues nothing when p is false.
__device__ __forceinline__ float4 ldcs_if(const float4* p, float x)
{
    float4 v;
    asm volatile(
        "{\n\t"
        ".reg .pred p;\n\t"
        "setp.ne.f32 p, %4, 0f00000000;\n\t"
        "mov.f32 %0, 0f00000000;\n\t"
        "mov.f32 %1, 0f00000000;\n\t"
        "mov.f32 %2, 0f00000000;\n\t"
        "mov.f32 %3, 0f00000000;\n\t"
        "@p ld.global.cs.v4.f32 {%0, %1, %2, %3}, [%5];\n\t"
        "}"
        : "=f"(v.x), "=f"(v.y), "=f"(v.z), "=f"(v.w)
        : "f"(x), "l"(p));
    return v;
}

__global__ __launch_bounds__(256, 8) __cluster_dims__(2, 1, 1)
void hypermlp_kernel(const float* __restrict__ z,
                     const float* __restrict__ xq,
                     float* __restrict__ out)
{
    cg::cluster_group cluster = cg::this_cluster();
    const int r    = (int)cluster.block_rank();   // 0 or 1
    const int peer = r ^ 1;
    const int b    = blockIdx.x >> 1;             // sample
    const float* __restrict__ zb = z + (size_t)b * TOTAL_PARAMS;
    const int t = threadIdx.x;                    // 0..255

    __shared__ float xs[2][512];                  // double-buffered activations
    __shared__ float red[1024];                   // 4KB partial-sum buffer

    float (*pxs)[512] = (float (*)[512])cluster.map_shared_rank(xs, peer);

    if (t < 128) xs[0][t] = xq[b * 128 + t];
    __syncthreads();

    const int o = r * 256 + t;                    // this thread's output index

    // ---------------- Layer 1: din=128 (dense input), dout=512 ----------------
    {
        const float4* __restrict__ wv = (const float4*)(zb + W1_OFF); // row=128 f4
        const int lane = t & 63;                  // 64 float4 = 256 outputs
        const int g    = t >> 6;                  // 4 groups x 32 i
        float4 acc = make_float4(0.f, 0.f, 0.f, 0.f);
        #pragma unroll 8
        for (int i = g * 32; i < g * 32 + 32; ++i) {
            const float xi = xs[0][i];
            const float4 wq = __ldcs(&wv[i * 128 + r * 64 + lane]);
            acc.x = fmaf(xi, wq.x, acc.x);
            acc.y = fmaf(xi, wq.y, acc.y);
            acc.z = fmaf(xi, wq.z, acc.z);
            acc.w = fmaf(xi, wq.w, acc.w);
        }
        ((float4*)(red + g * 256))[lane] = acc;
        __syncthreads();
        float v = zb[B1_OFF + o];
        #pragma unroll
        for (int g2 = 0; g2 < 4; ++g2) v += red[g2 * 256 + t];
        v = fmaxf(v, 0.f);
        xs[1][o]  = v;
        pxs[1][o] = v;
        cluster.sync();
    }

    // ---------------- Layers 2 & 3: din=512 (relu-sparse), dout=512 -----------
    {
        const float* p = zb + W2_OFF;
        #pragma unroll 1
        for (int L = 0; L < 2; ++L) {
            const int cur = 1 - L;                // L2 reads buf1, L3 reads buf0
            const int nxt = L;
            const float4* __restrict__ wv = (const float4*)p;
            const float* __restrict__ bias = p + 512 * 512;
            const int lane = t & 63;
            const int g    = t >> 6;              // 4 groups x 128 i
            float4 acc = make_float4(0.f, 0.f, 0.f, 0.f);
            #pragma unroll 8
            for (int i = g * 128; i < g * 128 + 128; ++i) {
                const float xi = xs[cur][i];      // uniform across group
                const float4 wq = ldcs_if(&wv[i * 128 + r * 64 + lane], xi);
                acc.x = fmaf(xi, wq.x, acc.x);
                acc.y = fmaf(xi, wq.y, acc.y);
                acc.z = fmaf(xi, wq.z, acc.z);
                acc.w = fmaf(xi, wq.w, acc.w);
            }
            ((float4*)(red + g * 256))[lane] = acc;
            __syncthreads();
            float v = bias[o];
            #pragma unroll
            for (int g2 = 0; g2 < 4; ++g2) v += red[g2 * 256 + t];
            v = fmaxf(v, 0.f);
            xs[nxt][o]  = v;
            pxs[nxt][o] = v;
            cluster.sync();
            p += 512 * 512 + 512;
        }
    }

    // ---------------- Layer 4: din=512 (relu-sparse), dout=128, no relu -------
    {
        const float4* __restrict__ wv = (const float4*)(zb + W4_OFF); // row=32 f4
        const int lane = t & 15;                  // 16 float4 = 64 outputs
        const int g    = t >> 4;                  // 16 groups x 32 i
        float4 acc = make_float4(0.f, 0.f, 0.f, 0.f);
        #pragma unroll 8
        for (int i = g * 32; i < g * 32 + 32; ++i) {
            const float xi = xs[1][i];
            const float4 wq = ldcs_if(&wv[i * 32 + r * 16 + lane], xi);
            acc.x = fmaf(xi, wq.x, acc.x);
            acc.y = fmaf(xi, wq.y, acc.y);
            acc.z = fmaf(xi, wq.z, acc.z);
            acc.w = fmaf(xi, wq.w, acc.w);
        }
        ((float4*)(red + g * 64))[lane] = acc;    // red as [16][64]
        __syncthreads();
        if (t < 64) {
            float v = zb[B4_OFF + r * 64 + t];
            #pragma unroll
            for (int g2 = 0; g2 < 16; ++g2) v += red[g2 * 64 + t];
            out[b * 128 + r * 64 + t] = v;
        }
    }
}

extern "C" void kernel_launch(void* const* d_in, const int* in_sizes, int n_in,
                              void* d_out, int out_size)
{
    const float* z  = (const float*)d_in[0];
    const float* xq = (const float*)d_in[1];
    if (n_in >= 2 && in_sizes[0] == NBATCH * 128) {
        z  = (const float*)d_in[1];
        xq = (const float*)d_in[0];
    }
    float* out = (float*)d_out;
    hypermlp_kernel<<<NBATCH * 2, 256>>>(z, xq, out);
}